// round 3
// baseline (speedup 1.0000x reference)
#include <cuda_runtime.h>
#include <math.h>

#define TILE 32
#define NT   128
#define ROWS 8          // rows per thread (warp w owns rows 8w..8w+7)
#define HD   128
#define OD   32
#define IND  64
#define BMAX 16384
#define MAXLVL 6

typedef unsigned long long ull;

// -------- device scratch (no allocations allowed) --------
__device__ float g_ha  [(size_t)MAXLVL * BMAX * HD];
__device__ float g_hai [(size_t)MAXLVL * BMAX * HD];
__device__ float g_prob[(size_t)MAXLVL * BMAX * OD];

__device__ __forceinline__ float sigm(float x) { return 1.0f / (1.0f + __expf(-x)); }

// ---- packed fp32x2 helpers (sm_103a) ----
__device__ __forceinline__ ull pack2(float lo, float hi) {
    ull r; asm("mov.b64 %0, {%1, %2};" : "=l"(r) : "f"(lo), "f"(hi)); return r;
}
__device__ __forceinline__ void unpack2(ull v, float& lo, float& hi) {
    asm("mov.b64 {%0, %1}, %2;" : "=f"(lo), "=f"(hi) : "l"(v));
}
__device__ __forceinline__ ull dup2(float x) {
    ull r; asm("mov.b64 %0, {%1, %1};" : "=l"(r) : "f"(x)); return r;
}
__device__ __forceinline__ ull fma2(ull a, ull b, ull c) {
    ull d; asm("fma.rn.f32x2 %0, %1, %2, %3;" : "=l"(d) : "l"(a), "l"(b), "l"(c)); return d;
}

// ============================================================
// init: h0 = z @ z2h_w + z2h_b     [B,64] @ [64,128]
// ============================================================
__global__ __launch_bounds__(NT, 2)
void init_kernel(const float* __restrict__ z, const float* __restrict__ Wz,
                 const float* __restrict__ bz, float* __restrict__ h0)
{
    __shared__ __align__(16) float zs[TILE][IND + 4];
    const int row0 = blockIdx.x * TILE;
    const int tid  = threadIdx.x;

    for (int i = tid; i < TILE * (IND / 4); i += NT) {
        int r = i >> 4, c = i & 15;
        float4 v = reinterpret_cast<const float4*>(z + (size_t)(row0 + r) * IND)[c];
        *reinterpret_cast<float4*>(&zs[r][c * 4]) = v;
    }
    __syncthreads();

    const int w = tid >> 5, l = tid & 31;
    const int rb = w * ROWS;
    ull acc[ROWS][2];
    {
        ulonglong2 b = *reinterpret_cast<const ulonglong2*>(bz + 4 * l);
        #pragma unroll
        for (int i = 0; i < ROWS; ++i) { acc[i][0] = b.x; acc[i][1] = b.y; }
    }
    #pragma unroll 2
    for (int k = 0; k < IND; ++k) {
        ulonglong2 t = *reinterpret_cast<const ulonglong2*>(Wz + k * HD + 4 * l);
        #pragma unroll
        for (int i = 0; i < ROWS; ++i) {
            ull zv = dup2(zs[rb + i][k]);
            acc[i][0] = fma2(zv, t.x, acc[i][0]);
            acc[i][1] = fma2(zv, t.y, acc[i][1]);
        }
    }
    #pragma unroll
    for (int i = 0; i < ROWS; ++i) {
        float x0, x1, x2, x3;
        unpack2(acc[i][0], x0, x1); unpack2(acc[i][1], x2, x3);
        *reinterpret_cast<float4*>(h0 + (size_t)(row0 + rb + i) * HD + 4 * l)
            = make_float4(x0, x1, x2, x3);
    }
}

// ============================================================
// node: pred = h@Wo+bo (emit), probs = softmax(pred),
//       h_ai = GRU_a(probs, h)
// ============================================================
__global__ __launch_bounds__(NT, 2)
void node_kernel(const float* __restrict__ hin,
                 const float* __restrict__ Wo, const float* __restrict__ bo,
                 const float* __restrict__ Wi, const float* __restrict__ bi,
                 const float* __restrict__ Wh, const float* __restrict__ bh,
                 float* __restrict__ pred_out, float* __restrict__ probs_out,
                 float* __restrict__ hout)
{
    __shared__ __align__(16) float hs[TILE][HD + 4];
    __shared__ __align__(16) float ps[TILE][OD + 4];
    const int row0 = blockIdx.x * TILE;
    const int tid  = threadIdx.x;

    for (int i = tid; i < TILE * (HD / 4); i += NT) {
        int r = i >> 5, c = i & 31;
        float4 v = reinterpret_cast<const float4*>(hin + (size_t)(row0 + r) * HD)[c];
        *reinterpret_cast<float4*>(&hs[r][c * 4]) = v;
    }
    __syncthreads();

    // ---- pred + softmax (warp-local: warp w computes rows 8w..8w+7) ----
    {
        const int r = tid >> 2, q = tid & 3;   // 4 lanes/row, 8 cols each
        ull a0, a1, a2, a3;
        {
            ulonglong2 b0 = *reinterpret_cast<const ulonglong2*>(bo + q * 8);
            ulonglong2 b1 = *reinterpret_cast<const ulonglong2*>(bo + q * 8 + 4);
            a0 = b0.x; a1 = b0.y; a2 = b1.x; a3 = b1.y;
        }
        #pragma unroll 4
        for (int k = 0; k < HD; ++k) {
            ulonglong2 t0 = *reinterpret_cast<const ulonglong2*>(Wo + k * OD + q * 8);
            ulonglong2 t1 = *reinterpret_cast<const ulonglong2*>(Wo + k * OD + q * 8 + 4);
            ull hv = dup2(hs[r][k]);
            a0 = fma2(hv, t0.x, a0); a1 = fma2(hv, t0.y, a1);
            a2 = fma2(hv, t1.x, a2); a3 = fma2(hv, t1.y, a3);
        }
        float acc[8];
        unpack2(a0, acc[0], acc[1]); unpack2(a1, acc[2], acc[3]);
        unpack2(a2, acc[4], acc[5]); unpack2(a3, acc[6], acc[7]);
        float* po = pred_out + (size_t)(row0 + r) * OD;
        *reinterpret_cast<float4*>(po + q * 8)     = make_float4(acc[0], acc[1], acc[2], acc[3]);
        *reinterpret_cast<float4*>(po + q * 8 + 4) = make_float4(acc[4], acc[5], acc[6], acc[7]);

        float m = acc[0];
        #pragma unroll
        for (int j = 1; j < 8; ++j) m = fmaxf(m, acc[j]);
        m = fmaxf(m, __shfl_xor_sync(0xffffffffu, m, 1));
        m = fmaxf(m, __shfl_xor_sync(0xffffffffu, m, 2));
        float s = 0.0f;
        #pragma unroll
        for (int j = 0; j < 8; ++j) { acc[j] = __expf(acc[j] - m); s += acc[j]; }
        s += __shfl_xor_sync(0xffffffffu, s, 1);
        s += __shfl_xor_sync(0xffffffffu, s, 2);
        float inv = 1.0f / s;
        float* qo = probs_out + (size_t)(row0 + r) * OD;
        float pv[8];
        #pragma unroll
        for (int j = 0; j < 8; ++j) { pv[j] = acc[j] * inv; ps[r][q * 8 + j] = pv[j]; }
        *reinterpret_cast<float4*>(qo + q * 8)     = make_float4(pv[0], pv[1], pv[2], pv[3]);
        *reinterpret_cast<float4*>(qo + q * 8 + 4) = make_float4(pv[4], pv[5], pv[6], pv[7]);
    }
    __syncwarp();   // ps rows are warp-local

    // ---- GRU_a: warp w rows 8w..8w+7, lane l cols 4l..4l+3 ----
    const int w = tid >> 5, l = tid & 31;
    const int rb = w * ROWS;
    const float* Wi0 = Wi;  const float* Wi1 = Wi + OD * HD;  const float* Wi2 = Wi + 2 * OD * HD;
    const float* Wh0 = Wh;  const float* Wh1 = Wh + HD * HD;  const float* Wh2 = Wh + 2 * HD * HD;

    ull a0[ROWS][2], a1[ROWS][2], a2i[ROWS][2], a2h[ROWS][2];
    #pragma unroll
    for (int i = 0; i < ROWS; ++i) {
        a0[i][0] = a0[i][1] = 0; a1[i][0] = a1[i][1] = 0;
        a2i[i][0] = a2i[i][1] = 0; a2h[i][0] = a2h[i][1] = 0;
    }

    #pragma unroll 2
    for (int k = 0; k < OD; ++k) {
        ulonglong2 t0 = *reinterpret_cast<const ulonglong2*>(Wi0 + k * HD + 4 * l);
        ulonglong2 t1 = *reinterpret_cast<const ulonglong2*>(Wi1 + k * HD + 4 * l);
        ulonglong2 t2 = *reinterpret_cast<const ulonglong2*>(Wi2 + k * HD + 4 * l);
        #pragma unroll
        for (int i = 0; i < ROWS; ++i) {
            ull pv = dup2(ps[rb + i][k]);
            a0[i][0]  = fma2(pv, t0.x, a0[i][0]);  a0[i][1]  = fma2(pv, t0.y, a0[i][1]);
            a1[i][0]  = fma2(pv, t1.x, a1[i][0]);  a1[i][1]  = fma2(pv, t1.y, a1[i][1]);
            a2i[i][0] = fma2(pv, t2.x, a2i[i][0]); a2i[i][1] = fma2(pv, t2.y, a2i[i][1]);
        }
    }
    #pragma unroll 2
    for (int k = 0; k < HD; ++k) {
        ulonglong2 t0 = *reinterpret_cast<const ulonglong2*>(Wh0 + k * HD + 4 * l);
        ulonglong2 t1 = *reinterpret_cast<const ulonglong2*>(Wh1 + k * HD + 4 * l);
        ulonglong2 t2 = *reinterpret_cast<const ulonglong2*>(Wh2 + k * HD + 4 * l);
        #pragma unroll
        for (int i = 0; i < ROWS; ++i) {
            ull hv = dup2(hs[rb + i][k]);
            a0[i][0]  = fma2(hv, t0.x, a0[i][0]);  a0[i][1]  = fma2(hv, t0.y, a0[i][1]);
            a1[i][0]  = fma2(hv, t1.x, a1[i][0]);  a1[i][1]  = fma2(hv, t1.y, a1[i][1]);
            a2h[i][0] = fma2(hv, t2.x, a2h[i][0]); a2h[i][1] = fma2(hv, t2.y, a2h[i][1]);
        }
    }

    float bi0[4], bi1[4], bi2[4], bh0[4], bh1[4], bh2[4];
    { float4 t = *reinterpret_cast<const float4*>(bi + 0 * HD + 4 * l); bi0[0]=t.x; bi0[1]=t.y; bi0[2]=t.z; bi0[3]=t.w; }
    { float4 t = *reinterpret_cast<const float4*>(bi + 1 * HD + 4 * l); bi1[0]=t.x; bi1[1]=t.y; bi1[2]=t.z; bi1[3]=t.w; }
    { float4 t = *reinterpret_cast<const float4*>(bi + 2 * HD + 4 * l); bi2[0]=t.x; bi2[1]=t.y; bi2[2]=t.z; bi2[3]=t.w; }
    { float4 t = *reinterpret_cast<const float4*>(bh + 0 * HD + 4 * l); bh0[0]=t.x; bh0[1]=t.y; bh0[2]=t.z; bh0[3]=t.w; }
    { float4 t = *reinterpret_cast<const float4*>(bh + 1 * HD + 4 * l); bh1[0]=t.x; bh1[1]=t.y; bh1[2]=t.z; bh1[3]=t.w; }
    { float4 t = *reinterpret_cast<const float4*>(bh + 2 * HD + 4 * l); bh2[0]=t.x; bh2[1]=t.y; bh2[2]=t.z; bh2[3]=t.w; }

    #pragma unroll
    for (int i = 0; i < ROWS; ++i) {
        float out[4];
        #pragma unroll
        for (int pr = 0; pr < 2; ++pr) {
            float g0a, g0b, g1a, g1b, nia, nib, nha, nhb;
            unpack2(a0[i][pr], g0a, g0b);  unpack2(a1[i][pr], g1a, g1b);
            unpack2(a2i[i][pr], nia, nib); unpack2(a2h[i][pr], nha, nhb);
            int j0 = pr * 2;
            {
                float rg = sigm(g0a + bi0[j0] + bh0[j0]);
                float zg = sigm(g1a + bi1[j0] + bh1[j0]);
                float ng = tanhf(nia + bi2[j0] + rg * (nha + bh2[j0]));
                float hv = hs[rb + i][4 * l + j0];
                out[j0] = (1.0f - zg) * ng + zg * hv;
            }
            {
                float rg = sigm(g0b + bi0[j0 + 1] + bh0[j0 + 1]);
                float zg = sigm(g1b + bi1[j0 + 1] + bh1[j0 + 1]);
                float ng = tanhf(nib + bi2[j0 + 1] + rg * (nhb + bh2[j0 + 1]));
                float hv = hs[rb + i][4 * l + j0 + 1];
                out[j0 + 1] = (1.0f - zg) * ng + zg * hv;
            }
        }
        *reinterpret_cast<float4*>(hout + (size_t)(row0 + rb + i) * HD + 4 * l)
            = make_float4(out[0], out[1], out[2], out[3]);
    }
}

// ============================================================
// frat: h_f = GRU_f(probs_f, h_ai);
//       h2  = tanh(h_f @ u_f_w + u_f_b + h_a @ u_a_w + u_a_b)
// ============================================================
__global__ __launch_bounds__(NT, 2)
void frat_kernel(const float* __restrict__ probsf,
                 const float* __restrict__ haif,
                 const float* __restrict__ hA,
                 const float* __restrict__ Wi, const float* __restrict__ bi,
                 const float* __restrict__ Wh, const float* __restrict__ bh,
                 const float* __restrict__ ufw, const float* __restrict__ ufb,
                 const float* __restrict__ uaw, const float* __restrict__ uab,
                 float* __restrict__ hout)
{
    __shared__ __align__(16) float hs [TILE][HD + 4];  // h_ai, overwritten with h_f
    __shared__ __align__(16) float has[TILE][HD + 4];  // h_a (ancestral)
    __shared__ __align__(16) float ps [TILE][OD + 4];
    const int row0 = blockIdx.x * TILE;
    const int tid  = threadIdx.x;

    for (int i = tid; i < TILE * (HD / 4); i += NT) {
        int r = i >> 5, c = i & 31;
        float4 v = reinterpret_cast<const float4*>(haif + (size_t)(row0 + r) * HD)[c];
        *reinterpret_cast<float4*>(&hs[r][c * 4]) = v;
        float4 u = reinterpret_cast<const float4*>(hA + (size_t)(row0 + r) * HD)[c];
        *reinterpret_cast<float4*>(&has[r][c * 4]) = u;
    }
    for (int i = tid; i < TILE * (OD / 4); i += NT) {
        int r = i >> 3, c = i & 7;
        float4 v = reinterpret_cast<const float4*>(probsf + (size_t)(row0 + r) * OD)[c];
        *reinterpret_cast<float4*>(&ps[r][c * 4]) = v;
    }
    __syncthreads();

    const int w = tid >> 5, l = tid & 31;
    const int rb = w * ROWS;
    const float* Wi0 = Wi;  const float* Wi1 = Wi + OD * HD;  const float* Wi2 = Wi + 2 * OD * HD;
    const float* Wh0 = Wh;  const float* Wh1 = Wh + HD * HD;  const float* Wh2 = Wh + 2 * HD * HD;

    // ---- phase 1: GRU_f, h_f written in place over hs (rows warp-private) ----
    {
        ull a0[ROWS][2], a1[ROWS][2], a2i[ROWS][2], a2h[ROWS][2];
        #pragma unroll
        for (int i = 0; i < ROWS; ++i) {
            a0[i][0] = a0[i][1] = 0; a1[i][0] = a1[i][1] = 0;
            a2i[i][0] = a2i[i][1] = 0; a2h[i][0] = a2h[i][1] = 0;
        }
        #pragma unroll 2
        for (int k = 0; k < OD; ++k) {
            ulonglong2 t0 = *reinterpret_cast<const ulonglong2*>(Wi0 + k * HD + 4 * l);
            ulonglong2 t1 = *reinterpret_cast<const ulonglong2*>(Wi1 + k * HD + 4 * l);
            ulonglong2 t2 = *reinterpret_cast<const ulonglong2*>(Wi2 + k * HD + 4 * l);
            #pragma unroll
            for (int i = 0; i < ROWS; ++i) {
                ull pv = dup2(ps[rb + i][k]);
                a0[i][0]  = fma2(pv, t0.x, a0[i][0]);  a0[i][1]  = fma2(pv, t0.y, a0[i][1]);
                a1[i][0]  = fma2(pv, t1.x, a1[i][0]);  a1[i][1]  = fma2(pv, t1.y, a1[i][1]);
                a2i[i][0] = fma2(pv, t2.x, a2i[i][0]); a2i[i][1] = fma2(pv, t2.y, a2i[i][1]);
            }
        }
        #pragma unroll 2
        for (int k = 0; k < HD; ++k) {
            ulonglong2 t0 = *reinterpret_cast<const ulonglong2*>(Wh0 + k * HD + 4 * l);
            ulonglong2 t1 = *reinterpret_cast<const ulonglong2*>(Wh1 + k * HD + 4 * l);
            ulonglong2 t2 = *reinterpret_cast<const ulonglong2*>(Wh2 + k * HD + 4 * l);
            #pragma unroll
            for (int i = 0; i < ROWS; ++i) {
                ull hv = dup2(hs[rb + i][k]);
                a0[i][0]  = fma2(hv, t0.x, a0[i][0]);  a0[i][1]  = fma2(hv, t0.y, a0[i][1]);
                a1[i][0]  = fma2(hv, t1.x, a1[i][0]);  a1[i][1]  = fma2(hv, t1.y, a1[i][1]);
                a2h[i][0] = fma2(hv, t2.x, a2h[i][0]); a2h[i][1] = fma2(hv, t2.y, a2h[i][1]);
            }
        }

        float bi0[4], bi1[4], bi2[4], bh0[4], bh1[4], bh2[4];
        { float4 t = *reinterpret_cast<const float4*>(bi + 0 * HD + 4 * l); bi0[0]=t.x; bi0[1]=t.y; bi0[2]=t.z; bi0[3]=t.w; }
        { float4 t = *reinterpret_cast<const float4*>(bi + 1 * HD + 4 * l); bi1[0]=t.x; bi1[1]=t.y; bi1[2]=t.z; bi1[3]=t.w; }
        { float4 t = *reinterpret_cast<const float4*>(bi + 2 * HD + 4 * l); bi2[0]=t.x; bi2[1]=t.y; bi2[2]=t.z; bi2[3]=t.w; }
        { float4 t = *reinterpret_cast<const float4*>(bh + 0 * HD + 4 * l); bh0[0]=t.x; bh0[1]=t.y; bh0[2]=t.z; bh0[3]=t.w; }
        { float4 t = *reinterpret_cast<const float4*>(bh + 1 * HD + 4 * l); bh1[0]=t.x; bh1[1]=t.y; bh1[2]=t.z; bh1[3]=t.w; }
        { float4 t = *reinterpret_cast<const float4*>(bh + 2 * HD + 4 * l); bh2[0]=t.x; bh2[1]=t.y; bh2[2]=t.z; bh2[3]=t.w; }

        float hf[ROWS][4];
        #pragma unroll
        for (int i = 0; i < ROWS; ++i) {
            #pragma unroll
            for (int pr = 0; pr < 2; ++pr) {
                float g0a, g0b, g1a, g1b, nia, nib, nha, nhb;
                unpack2(a0[i][pr], g0a, g0b);  unpack2(a1[i][pr], g1a, g1b);
                unpack2(a2i[i][pr], nia, nib); unpack2(a2h[i][pr], nha, nhb);
                int j0 = pr * 2;
                {
                    float rg = sigm(g0a + bi0[j0] + bh0[j0]);
                    float zg = sigm(g1a + bi1[j0] + bh1[j0]);
                    float ng = tanhf(nia + bi2[j0] + rg * (nha + bh2[j0]));
                    float hv = hs[rb + i][4 * l + j0];
                    hf[i][j0] = (1.0f - zg) * ng + zg * hv;
                }
                {
                    float rg = sigm(g0b + bi0[j0 + 1] + bh0[j0 + 1]);
                    float zg = sigm(g1b + bi1[j0 + 1] + bh1[j0 + 1]);
                    float ng = tanhf(nib + bi2[j0 + 1] + rg * (nhb + bh2[j0 + 1]));
                    float hv = hs[rb + i][4 * l + j0 + 1];
                    hf[i][j0 + 1] = (1.0f - zg) * ng + zg * hv;
                }
            }
        }
        __syncwarp();   // warp done reading its rows before overwrite
        #pragma unroll
        for (int i = 0; i < ROWS; ++i)
            #pragma unroll
            for (int j = 0; j < 4; ++j) hs[rb + i][4 * l + j] = hf[i][j];
        __syncwarp();
    }

    // ---- phase 2: h2 = tanh(h_f @ ufw + ufb + h_a @ uaw + uab) ----
    {
        ull acc[ROWS][2];
        {
            float4 tf = *reinterpret_cast<const float4*>(ufb + 4 * l);
            float4 ta = *reinterpret_cast<const float4*>(uab + 4 * l);
            ull b0 = pack2(tf.x + ta.x, tf.y + ta.y);
            ull b1 = pack2(tf.z + ta.z, tf.w + ta.w);
            #pragma unroll
            for (int i = 0; i < ROWS; ++i) { acc[i][0] = b0; acc[i][1] = b1; }
        }
        #pragma unroll 2
        for (int k = 0; k < HD; ++k) {
            ulonglong2 tf = *reinterpret_cast<const ulonglong2*>(ufw + k * HD + 4 * l);
            ulonglong2 ta = *reinterpret_cast<const ulonglong2*>(uaw + k * HD + 4 * l);
            #pragma unroll
            for (int i = 0; i < ROWS; ++i) {
                ull hfv = dup2(hs[rb + i][k]);
                ull hav = dup2(has[rb + i][k]);
                acc[i][0] = fma2(hfv, tf.x, acc[i][0]); acc[i][1] = fma2(hfv, tf.y, acc[i][1]);
                acc[i][0] = fma2(hav, ta.x, acc[i][0]); acc[i][1] = fma2(hav, ta.y, acc[i][1]);
            }
        }
        #pragma unroll
        for (int i = 0; i < ROWS; ++i) {
            float x0, x1, x2, x3;
            unpack2(acc[i][0], x0, x1); unpack2(acc[i][1], x2, x3);
            *reinterpret_cast<float4*>(hout + (size_t)(row0 + rb + i) * HD + 4 * l)
                = make_float4(tanhf(x0), tanhf(x1), tanhf(x2), tanhf(x3));
        }
    }
}

// ============================================================
// host: preorder scheduler
// ============================================================
struct SchedCtx {
    const float* in[18];
    float* out;
    float *ha, *hai, *prob;
    int B, grid, idx;
};

static void sched_node(SchedCtx& S, int lvl, const float* hA, int d)
{
    node_kernel<<<S.grid, NT>>>(hA,
        S.in[3], S.in[4],                       // h2o_w, h2o_b
        S.in[5], S.in[6], S.in[7], S.in[8],     // gru_a wi, bi, wh, bh
        S.out + (size_t)S.idx * S.B * OD,
        S.prob + (size_t)lvl * S.B * OD,
        S.hai  + (size_t)lvl * S.B * HD);
    S.idx++;
    if (d > 0) {
        const float* h_ai = S.hai + (size_t)lvl * S.B * HD;
        sched_node(S, lvl + 1, h_ai, d - 1);                       // first child
        frat_kernel<<<S.grid, NT>>>(
            S.prob + (size_t)(lvl + 1) * S.B * OD,                  // first child's probs
            h_ai, hA,
            S.in[9], S.in[10], S.in[11], S.in[12],                  // gru_f wi, bi, wh, bh
            S.in[15], S.in[16],                                     // u_f_w, u_f_b
            S.in[13], S.in[14],                                     // u_a_w, u_a_b
            S.ha + (size_t)(lvl + 1) * S.B * HD);
        sched_node(S, lvl + 1, S.ha + (size_t)(lvl + 1) * S.B * HD, d - 1);  // second child
    }
}

extern "C" void kernel_launch(void* const* d_in, const int* in_sizes, int n_in,
                              void* d_out, int out_size)
{
    SchedCtx S;
    for (int i = 0; i < n_in && i < 18; ++i) S.in[i] = (const float*)d_in[i];
    S.out = (float*)d_out;
    S.B = in_sizes[0] / IND;
    if (S.B <= 0 || S.B > BMAX) return;
    S.grid = S.B / TILE;
    S.idx = 0;

    int n_nodes = out_size / (S.B * OD);
    int depth = 0; { int nn = 1; while (nn < n_nodes && depth < MAXLVL - 1) { nn = 2 * nn + 1; depth++; } }

    cudaGetSymbolAddress((void**)&S.ha,   g_ha);
    cudaGetSymbolAddress((void**)&S.hai,  g_hai);
    cudaGetSymbolAddress((void**)&S.prob, g_prob);

    init_kernel<<<S.grid, NT>>>(S.in[0], S.in[1], S.in[2], S.ha);
    sched_node(S, 0, S.ha, depth);
}

// round 4
// speedup vs baseline: 1.0003x; 1.0003x over previous
#include <cuda_runtime.h>
#include <math.h>

#define TILE 32
#define NT   128
#define ROWS 8          // rows per thread (warp w owns rows 8w..8w+7)
#define HD   128
#define OD   32
#define IND  64
#define BMAX 16384
#define MAXLVL 6

typedef unsigned long long ull;

// -------- device scratch (no allocations allowed) --------
__device__ float g_ha  [(size_t)MAXLVL * BMAX * HD];
__device__ float g_hai [(size_t)MAXLVL * BMAX * HD];
__device__ float g_prob[(size_t)MAXLVL * BMAX * OD];

__device__ __forceinline__ float sigm(float x) { return 1.0f / (1.0f + __expf(-x)); }

// ---- packed fp32x2 helpers (sm_103a) ----
__device__ __forceinline__ ull pack2(float lo, float hi) {
    ull r; asm("mov.b64 %0, {%1, %2};" : "=l"(r) : "f"(lo), "f"(hi)); return r;
}
__device__ __forceinline__ void unpack2(ull v, float& lo, float& hi) {
    asm("mov.b64 {%0, %1}, %2;" : "=f"(lo), "=f"(hi) : "l"(v));
}
__device__ __forceinline__ ull dup2(float x) {
    ull r; asm("mov.b64 %0, {%1, %1};" : "=l"(r) : "f"(x)); return r;
}
__device__ __forceinline__ ull fma2(ull a, ull b, ull c) {
    ull d; asm("fma.rn.f32x2 %0, %1, %2, %3;" : "=l"(d) : "l"(a), "l"(b), "l"(c)); return d;
}

// ============================================================
// init: h0 = z @ z2h_w + z2h_b     [B,64] @ [64,128]
// ============================================================
__global__ __launch_bounds__(NT, 2)
void init_kernel(const float* __restrict__ z, const float* __restrict__ Wz,
                 const float* __restrict__ bz, float* __restrict__ h0)
{
    __shared__ __align__(16) float zs[TILE][IND + 4];
    const int row0 = blockIdx.x * TILE;
    const int tid  = threadIdx.x;

    for (int i = tid; i < TILE * (IND / 4); i += NT) {
        int r = i >> 4, c = i & 15;
        float4 v = reinterpret_cast<const float4*>(z + (size_t)(row0 + r) * IND)[c];
        *reinterpret_cast<float4*>(&zs[r][c * 4]) = v;
    }
    __syncthreads();

    const int w = tid >> 5, l = tid & 31;
    const int rb = w * ROWS;
    ull acc[ROWS][2];
    {
        ulonglong2 b = *reinterpret_cast<const ulonglong2*>(bz + 4 * l);
        #pragma unroll
        for (int i = 0; i < ROWS; ++i) { acc[i][0] = b.x; acc[i][1] = b.y; }
    }
    #pragma unroll 2
    for (int k = 0; k < IND; ++k) {
        ulonglong2 t = *reinterpret_cast<const ulonglong2*>(Wz + k * HD + 4 * l);
        #pragma unroll
        for (int i = 0; i < ROWS; ++i) {
            ull zv = dup2(zs[rb + i][k]);
            acc[i][0] = fma2(zv, t.x, acc[i][0]);
            acc[i][1] = fma2(zv, t.y, acc[i][1]);
        }
    }
    #pragma unroll
    for (int i = 0; i < ROWS; ++i) {
        float x0, x1, x2, x3;
        unpack2(acc[i][0], x0, x1); unpack2(acc[i][1], x2, x3);
        *reinterpret_cast<float4*>(h0 + (size_t)(row0 + rb + i) * HD + 4 * l)
            = make_float4(x0, x1, x2, x3);
    }
}

// ============================================================
// node: pred = h@Wo+bo (emit), probs = softmax(pred),
//       h_ai = GRU_a(probs, h)
// ============================================================
__global__ __launch_bounds__(NT, 2)
void node_kernel(const float* __restrict__ hin,
                 const float* __restrict__ Wo, const float* __restrict__ bo,
                 const float* __restrict__ Wi, const float* __restrict__ bi,
                 const float* __restrict__ Wh, const float* __restrict__ bh,
                 float* __restrict__ pred_out, float* __restrict__ probs_out,
                 float* __restrict__ hout)
{
    __shared__ __align__(16) float hs[TILE][HD + 4];
    __shared__ __align__(16) float ps[TILE][OD + 4];
    const int row0 = blockIdx.x * TILE;
    const int tid  = threadIdx.x;

    for (int i = tid; i < TILE * (HD / 4); i += NT) {
        int r = i >> 5, c = i & 31;
        float4 v = reinterpret_cast<const float4*>(hin + (size_t)(row0 + r) * HD)[c];
        *reinterpret_cast<float4*>(&hs[r][c * 4]) = v;
    }
    __syncthreads();

    // ---- pred + softmax (warp-local: warp w computes rows 8w..8w+7) ----
    {
        const int r = tid >> 2, q = tid & 3;   // 4 lanes/row, 8 cols each
        ull a0, a1, a2, a3;
        {
            ulonglong2 b0 = *reinterpret_cast<const ulonglong2*>(bo + q * 8);
            ulonglong2 b1 = *reinterpret_cast<const ulonglong2*>(bo + q * 8 + 4);
            a0 = b0.x; a1 = b0.y; a2 = b1.x; a3 = b1.y;
        }
        #pragma unroll 4
        for (int k = 0; k < HD; ++k) {
            ulonglong2 t0 = *reinterpret_cast<const ulonglong2*>(Wo + k * OD + q * 8);
            ulonglong2 t1 = *reinterpret_cast<const ulonglong2*>(Wo + k * OD + q * 8 + 4);
            ull hv = dup2(hs[r][k]);
            a0 = fma2(hv, t0.x, a0); a1 = fma2(hv, t0.y, a1);
            a2 = fma2(hv, t1.x, a2); a3 = fma2(hv, t1.y, a3);
        }
        float acc[8];
        unpack2(a0, acc[0], acc[1]); unpack2(a1, acc[2], acc[3]);
        unpack2(a2, acc[4], acc[5]); unpack2(a3, acc[6], acc[7]);
        float* po = pred_out + (size_t)(row0 + r) * OD;
        *reinterpret_cast<float4*>(po + q * 8)     = make_float4(acc[0], acc[1], acc[2], acc[3]);
        *reinterpret_cast<float4*>(po + q * 8 + 4) = make_float4(acc[4], acc[5], acc[6], acc[7]);

        float m = acc[0];
        #pragma unroll
        for (int j = 1; j < 8; ++j) m = fmaxf(m, acc[j]);
        m = fmaxf(m, __shfl_xor_sync(0xffffffffu, m, 1));
        m = fmaxf(m, __shfl_xor_sync(0xffffffffu, m, 2));
        float s = 0.0f;
        #pragma unroll
        for (int j = 0; j < 8; ++j) { acc[j] = __expf(acc[j] - m); s += acc[j]; }
        s += __shfl_xor_sync(0xffffffffu, s, 1);
        s += __shfl_xor_sync(0xffffffffu, s, 2);
        float inv = 1.0f / s;
        float* qo = probs_out + (size_t)(row0 + r) * OD;
        float pv[8];
        #pragma unroll
        for (int j = 0; j < 8; ++j) { pv[j] = acc[j] * inv; ps[r][q * 8 + j] = pv[j]; }
        *reinterpret_cast<float4*>(qo + q * 8)     = make_float4(pv[0], pv[1], pv[2], pv[3]);
        *reinterpret_cast<float4*>(qo + q * 8 + 4) = make_float4(pv[4], pv[5], pv[6], pv[7]);
    }
    __syncwarp();   // ps rows are warp-local

    // ---- GRU_a: warp w rows 8w..8w+7, lane l cols 4l..4l+3 ----
    const int w = tid >> 5, l = tid & 31;
    const int rb = w * ROWS;
    const float* Wi0 = Wi;  const float* Wi1 = Wi + OD * HD;  const float* Wi2 = Wi + 2 * OD * HD;
    const float* Wh0 = Wh;  const float* Wh1 = Wh + HD * HD;  const float* Wh2 = Wh + 2 * HD * HD;

    ull a0[ROWS][2], a1[ROWS][2], a2i[ROWS][2], a2h[ROWS][2];
    #pragma unroll
    for (int i = 0; i < ROWS; ++i) {
        a0[i][0] = a0[i][1] = 0; a1[i][0] = a1[i][1] = 0;
        a2i[i][0] = a2i[i][1] = 0; a2h[i][0] = a2h[i][1] = 0;
    }

    #pragma unroll 2
    for (int k = 0; k < OD; ++k) {
        ulonglong2 t0 = *reinterpret_cast<const ulonglong2*>(Wi0 + k * HD + 4 * l);
        ulonglong2 t1 = *reinterpret_cast<const ulonglong2*>(Wi1 + k * HD + 4 * l);
        ulonglong2 t2 = *reinterpret_cast<const ulonglong2*>(Wi2 + k * HD + 4 * l);
        #pragma unroll
        for (int i = 0; i < ROWS; ++i) {
            ull pv = dup2(ps[rb + i][k]);
            a0[i][0]  = fma2(pv, t0.x, a0[i][0]);  a0[i][1]  = fma2(pv, t0.y, a0[i][1]);
            a1[i][0]  = fma2(pv, t1.x, a1[i][0]);  a1[i][1]  = fma2(pv, t1.y, a1[i][1]);
            a2i[i][0] = fma2(pv, t2.x, a2i[i][0]); a2i[i][1] = fma2(pv, t2.y, a2i[i][1]);
        }
    }
    #pragma unroll 2
    for (int k = 0; k < HD; ++k) {
        ulonglong2 t0 = *reinterpret_cast<const ulonglong2*>(Wh0 + k * HD + 4 * l);
        ulonglong2 t1 = *reinterpret_cast<const ulonglong2*>(Wh1 + k * HD + 4 * l);
        ulonglong2 t2 = *reinterpret_cast<const ulonglong2*>(Wh2 + k * HD + 4 * l);
        #pragma unroll
        for (int i = 0; i < ROWS; ++i) {
            ull hv = dup2(hs[rb + i][k]);
            a0[i][0]  = fma2(hv, t0.x, a0[i][0]);  a0[i][1]  = fma2(hv, t0.y, a0[i][1]);
            a1[i][0]  = fma2(hv, t1.x, a1[i][0]);  a1[i][1]  = fma2(hv, t1.y, a1[i][1]);
            a2h[i][0] = fma2(hv, t2.x, a2h[i][0]); a2h[i][1] = fma2(hv, t2.y, a2h[i][1]);
        }
    }

    float bi0[4], bi1[4], bi2[4], bh0[4], bh1[4], bh2[4];
    { float4 t = *reinterpret_cast<const float4*>(bi + 0 * HD + 4 * l); bi0[0]=t.x; bi0[1]=t.y; bi0[2]=t.z; bi0[3]=t.w; }
    { float4 t = *reinterpret_cast<const float4*>(bi + 1 * HD + 4 * l); bi1[0]=t.x; bi1[1]=t.y; bi1[2]=t.z; bi1[3]=t.w; }
    { float4 t = *reinterpret_cast<const float4*>(bi + 2 * HD + 4 * l); bi2[0]=t.x; bi2[1]=t.y; bi2[2]=t.z; bi2[3]=t.w; }
    { float4 t = *reinterpret_cast<const float4*>(bh + 0 * HD + 4 * l); bh0[0]=t.x; bh0[1]=t.y; bh0[2]=t.z; bh0[3]=t.w; }
    { float4 t = *reinterpret_cast<const float4*>(bh + 1 * HD + 4 * l); bh1[0]=t.x; bh1[1]=t.y; bh1[2]=t.z; bh1[3]=t.w; }
    { float4 t = *reinterpret_cast<const float4*>(bh + 2 * HD + 4 * l); bh2[0]=t.x; bh2[1]=t.y; bh2[2]=t.z; bh2[3]=t.w; }

    #pragma unroll
    for (int i = 0; i < ROWS; ++i) {
        float out[4];
        #pragma unroll
        for (int pr = 0; pr < 2; ++pr) {
            float g0a, g0b, g1a, g1b, nia, nib, nha, nhb;
            unpack2(a0[i][pr], g0a, g0b);  unpack2(a1[i][pr], g1a, g1b);
            unpack2(a2i[i][pr], nia, nib); unpack2(a2h[i][pr], nha, nhb);
            int j0 = pr * 2;
            {
                float rg = sigm(g0a + bi0[j0] + bh0[j0]);
                float zg = sigm(g1a + bi1[j0] + bh1[j0]);
                float ng = tanhf(nia + bi2[j0] + rg * (nha + bh2[j0]));
                float hv = hs[rb + i][4 * l + j0];
                out[j0] = (1.0f - zg) * ng + zg * hv;
            }
            {
                float rg = sigm(g0b + bi0[j0 + 1] + bh0[j0 + 1]);
                float zg = sigm(g1b + bi1[j0 + 1] + bh1[j0 + 1]);
                float ng = tanhf(nib + bi2[j0 + 1] + rg * (nhb + bh2[j0 + 1]));
                float hv = hs[rb + i][4 * l + j0 + 1];
                out[j0 + 1] = (1.0f - zg) * ng + zg * hv;
            }
        }
        *reinterpret_cast<float4*>(hout + (size_t)(row0 + rb + i) * HD + 4 * l)
            = make_float4(out[0], out[1], out[2], out[3]);
    }
}

// ============================================================
// frat: h_f = GRU_f(probs_f, h_ai);
//       h2  = tanh(h_f @ u_f_w + u_f_b + h_a @ u_a_w + u_a_b)
// ============================================================
__global__ __launch_bounds__(NT, 2)
void frat_kernel(const float* __restrict__ probsf,
                 const float* __restrict__ haif,
                 const float* __restrict__ hA,
                 const float* __restrict__ Wi, const float* __restrict__ bi,
                 const float* __restrict__ Wh, const float* __restrict__ bh,
                 const float* __restrict__ ufw, const float* __restrict__ ufb,
                 const float* __restrict__ uaw, const float* __restrict__ uab,
                 float* __restrict__ hout)
{
    __shared__ __align__(16) float hs [TILE][HD + 4];  // h_ai, overwritten with h_f
    __shared__ __align__(16) float has[TILE][HD + 4];  // h_a (ancestral)
    __shared__ __align__(16) float ps [TILE][OD + 4];
    const int row0 = blockIdx.x * TILE;
    const int tid  = threadIdx.x;

    for (int i = tid; i < TILE * (HD / 4); i += NT) {
        int r = i >> 5, c = i & 31;
        float4 v = reinterpret_cast<const float4*>(haif + (size_t)(row0 + r) * HD)[c];
        *reinterpret_cast<float4*>(&hs[r][c * 4]) = v;
        float4 u = reinterpret_cast<const float4*>(hA + (size_t)(row0 + r) * HD)[c];
        *reinterpret_cast<float4*>(&has[r][c * 4]) = u;
    }
    for (int i = tid; i < TILE * (OD / 4); i += NT) {
        int r = i >> 3, c = i & 7;
        float4 v = reinterpret_cast<const float4*>(probsf + (size_t)(row0 + r) * OD)[c];
        *reinterpret_cast<float4*>(&ps[r][c * 4]) = v;
    }
    __syncthreads();

    const int w = tid >> 5, l = tid & 31;
    const int rb = w * ROWS;
    const float* Wi0 = Wi;  const float* Wi1 = Wi + OD * HD;  const float* Wi2 = Wi + 2 * OD * HD;
    const float* Wh0 = Wh;  const float* Wh1 = Wh + HD * HD;  const float* Wh2 = Wh + 2 * HD * HD;

    // ---- phase 1: GRU_f, h_f written in place over hs (rows warp-private) ----
    {
        ull a0[ROWS][2], a1[ROWS][2], a2i[ROWS][2], a2h[ROWS][2];
        #pragma unroll
        for (int i = 0; i < ROWS; ++i) {
            a0[i][0] = a0[i][1] = 0; a1[i][0] = a1[i][1] = 0;
            a2i[i][0] = a2i[i][1] = 0; a2h[i][0] = a2h[i][1] = 0;
        }
        #pragma unroll 2
        for (int k = 0; k < OD; ++k) {
            ulonglong2 t0 = *reinterpret_cast<const ulonglong2*>(Wi0 + k * HD + 4 * l);
            ulonglong2 t1 = *reinterpret_cast<const ulonglong2*>(Wi1 + k * HD + 4 * l);
            ulonglong2 t2 = *reinterpret_cast<const ulonglong2*>(Wi2 + k * HD + 4 * l);
            #pragma unroll
            for (int i = 0; i < ROWS; ++i) {
                ull pv = dup2(ps[rb + i][k]);
                a0[i][0]  = fma2(pv, t0.x, a0[i][0]);  a0[i][1]  = fma2(pv, t0.y, a0[i][1]);
                a1[i][0]  = fma2(pv, t1.x, a1[i][0]);  a1[i][1]  = fma2(pv, t1.y, a1[i][1]);
                a2i[i][0] = fma2(pv, t2.x, a2i[i][0]); a2i[i][1] = fma2(pv, t2.y, a2i[i][1]);
            }
        }
        #pragma unroll 2
        for (int k = 0; k < HD; ++k) {
            ulonglong2 t0 = *reinterpret_cast<const ulonglong2*>(Wh0 + k * HD + 4 * l);
            ulonglong2 t1 = *reinterpret_cast<const ulonglong2*>(Wh1 + k * HD + 4 * l);
            ulonglong2 t2 = *reinterpret_cast<const ulonglong2*>(Wh2 + k * HD + 4 * l);
            #pragma unroll
            for (int i = 0; i < ROWS; ++i) {
                ull hv = dup2(hs[rb + i][k]);
                a0[i][0]  = fma2(hv, t0.x, a0[i][0]);  a0[i][1]  = fma2(hv, t0.y, a0[i][1]);
                a1[i][0]  = fma2(hv, t1.x, a1[i][0]);  a1[i][1]  = fma2(hv, t1.y, a1[i][1]);
                a2h[i][0] = fma2(hv, t2.x, a2h[i][0]); a2h[i][1] = fma2(hv, t2.y, a2h[i][1]);
            }
        }

        float bi0[4], bi1[4], bi2[4], bh0[4], bh1[4], bh2[4];
        { float4 t = *reinterpret_cast<const float4*>(bi + 0 * HD + 4 * l); bi0[0]=t.x; bi0[1]=t.y; bi0[2]=t.z; bi0[3]=t.w; }
        { float4 t = *reinterpret_cast<const float4*>(bi + 1 * HD + 4 * l); bi1[0]=t.x; bi1[1]=t.y; bi1[2]=t.z; bi1[3]=t.w; }
        { float4 t = *reinterpret_cast<const float4*>(bi + 2 * HD + 4 * l); bi2[0]=t.x; bi2[1]=t.y; bi2[2]=t.z; bi2[3]=t.w; }
        { float4 t = *reinterpret_cast<const float4*>(bh + 0 * HD + 4 * l); bh0[0]=t.x; bh0[1]=t.y; bh0[2]=t.z; bh0[3]=t.w; }
        { float4 t = *reinterpret_cast<const float4*>(bh + 1 * HD + 4 * l); bh1[0]=t.x; bh1[1]=t.y; bh1[2]=t.z; bh1[3]=t.w; }
        { float4 t = *reinterpret_cast<const float4*>(bh + 2 * HD + 4 * l); bh2[0]=t.x; bh2[1]=t.y; bh2[2]=t.z; bh2[3]=t.w; }

        float hf[ROWS][4];
        #pragma unroll
        for (int i = 0; i < ROWS; ++i) {
            #pragma unroll
            for (int pr = 0; pr < 2; ++pr) {
                float g0a, g0b, g1a, g1b, nia, nib, nha, nhb;
                unpack2(a0[i][pr], g0a, g0b);  unpack2(a1[i][pr], g1a, g1b);
                unpack2(a2i[i][pr], nia, nib); unpack2(a2h[i][pr], nha, nhb);
                int j0 = pr * 2;
                {
                    float rg = sigm(g0a + bi0[j0] + bh0[j0]);
                    float zg = sigm(g1a + bi1[j0] + bh1[j0]);
                    float ng = tanhf(nia + bi2[j0] + rg * (nha + bh2[j0]));
                    float hv = hs[rb + i][4 * l + j0];
                    hf[i][j0] = (1.0f - zg) * ng + zg * hv;
                }
                {
                    float rg = sigm(g0b + bi0[j0 + 1] + bh0[j0 + 1]);
                    float zg = sigm(g1b + bi1[j0 + 1] + bh1[j0 + 1]);
                    float ng = tanhf(nib + bi2[j0 + 1] + rg * (nhb + bh2[j0 + 1]));
                    float hv = hs[rb + i][4 * l + j0 + 1];
                    hf[i][j0 + 1] = (1.0f - zg) * ng + zg * hv;
                }
            }
        }
        __syncwarp();   // warp done reading its rows before overwrite
        #pragma unroll
        for (int i = 0; i < ROWS; ++i)
            #pragma unroll
            for (int j = 0; j < 4; ++j) hs[rb + i][4 * l + j] = hf[i][j];
        __syncwarp();
    }

    // ---- phase 2: h2 = tanh(h_f @ ufw + ufb + h_a @ uaw + uab) ----
    {
        ull acc[ROWS][2];
        {
            float4 tf = *reinterpret_cast<const float4*>(ufb + 4 * l);
            float4 ta = *reinterpret_cast<const float4*>(uab + 4 * l);
            ull b0 = pack2(tf.x + ta.x, tf.y + ta.y);
            ull b1 = pack2(tf.z + ta.z, tf.w + ta.w);
            #pragma unroll
            for (int i = 0; i < ROWS; ++i) { acc[i][0] = b0; acc[i][1] = b1; }
        }
        #pragma unroll 2
        for (int k = 0; k < HD; ++k) {
            ulonglong2 tf = *reinterpret_cast<const ulonglong2*>(ufw + k * HD + 4 * l);
            ulonglong2 ta = *reinterpret_cast<const ulonglong2*>(uaw + k * HD + 4 * l);
            #pragma unroll
            for (int i = 0; i < ROWS; ++i) {
                ull hfv = dup2(hs[rb + i][k]);
                ull hav = dup2(has[rb + i][k]);
                acc[i][0] = fma2(hfv, tf.x, acc[i][0]); acc[i][1] = fma2(hfv, tf.y, acc[i][1]);
                acc[i][0] = fma2(hav, ta.x, acc[i][0]); acc[i][1] = fma2(hav, ta.y, acc[i][1]);
            }
        }
        #pragma unroll
        for (int i = 0; i < ROWS; ++i) {
            float x0, x1, x2, x3;
            unpack2(acc[i][0], x0, x1); unpack2(acc[i][1], x2, x3);
            *reinterpret_cast<float4*>(hout + (size_t)(row0 + rb + i) * HD + 4 * l)
                = make_float4(tanhf(x0), tanhf(x1), tanhf(x2), tanhf(x3));
        }
    }
}

// ============================================================
// host: preorder scheduler
// ============================================================
struct SchedCtx {
    const float* in[18];
    float* out;
    float *ha, *hai, *prob;
    int B, grid, idx;
};

static void sched_node(SchedCtx& S, int lvl, const float* hA, int d)
{
    node_kernel<<<S.grid, NT>>>(hA,
        S.in[3], S.in[4],                       // h2o_w, h2o_b
        S.in[5], S.in[6], S.in[7], S.in[8],     // gru_a wi, bi, wh, bh
        S.out + (size_t)S.idx * S.B * OD,
        S.prob + (size_t)lvl * S.B * OD,
        S.hai  + (size_t)lvl * S.B * HD);
    S.idx++;
    if (d > 0) {
        const float* h_ai = S.hai + (size_t)lvl * S.B * HD;
        sched_node(S, lvl + 1, h_ai, d - 1);                       // first child
        frat_kernel<<<S.grid, NT>>>(
            S.prob + (size_t)(lvl + 1) * S.B * OD,                  // first child's probs
            h_ai, hA,
            S.in[9], S.in[10], S.in[11], S.in[12],                  // gru_f wi, bi, wh, bh
            S.in[15], S.in[16],                                     // u_f_w, u_f_b
            S.in[13], S.in[14],                                     // u_a_w, u_a_b
            S.ha + (size_t)(lvl + 1) * S.B * HD);
        sched_node(S, lvl + 1, S.ha + (size_t)(lvl + 1) * S.B * HD, d - 1);  // second child
    }
}

extern "C" void kernel_launch(void* const* d_in, const int* in_sizes, int n_in,
                              void* d_out, int out_size)
{
    SchedCtx S;
    for (int i = 0; i < n_in && i < 18; ++i) S.in[i] = (const float*)d_in[i];
    S.out = (float*)d_out;
    S.B = in_sizes[0] / IND;
    if (S.B <= 0 || S.B > BMAX) return;
    S.grid = S.B / TILE;
    S.idx = 0;

    int n_nodes = out_size / (S.B * OD);
    int depth = 0; { int nn = 1; while (nn < n_nodes && depth < MAXLVL - 1) { nn = 2 * nn + 1; depth++; } }

    cudaGetSymbolAddress((void**)&S.ha,   g_ha);
    cudaGetSymbolAddress((void**)&S.hai,  g_hai);
    cudaGetSymbolAddress((void**)&S.prob, g_prob);

    init_kernel<<<S.grid, NT>>>(S.in[0], S.in[1], S.in[2], S.ha);
    sched_node(S, 0, S.ha, depth);
}